// round 12
// baseline (speedup 1.0000x reference)
#include <cuda_runtime.h>
#include <cuda_fp16.h>
#include <math.h>
#include <stdint.h>

// Problem constants (fixed by reference setup_inputs)
#define NN      8192          // nodes per graph
#define NT      16384         // stacked nodes (2 graphs)
#define DF      128           // feature dim
#define EE      131072        // edges per graph
#define GB      64            // graphs per batch
#define GNODES  128           // nodes per graph-block (NN/GB)
#define PAD     132           // smem row pad for attention kernels

// ---------------- scratch (static device globals; no allocation) -------------
__device__ __half g_AC [(size_t)NT * 1024];  // [A (512) | Cb (512)] per row, half
__device__ __half g_H  [(size_t)NT * 512];   // sum_e relu(A[src]+C[tgt]) (half)
__device__ __half g_U  [(size_t)NT * 512];   // [messages | att | x] (half)
__device__ __half g_H1 [(size_t)NT * 512];
__device__ __half g_H2 [(size_t)NT * 256];
__device__ float  g_XS [(size_t)NT * DF];    // stacked [x1; x2] FULL precision (residual)
__device__ __half g_XRh[(size_t)NT * DF];    // half copy (GEMM input)
__device__ float  g_P1 [(size_t)GB * GNODES * GNODES];
__device__ float  g_P2 [(size_t)GB * GNODES * GNODES];
__device__ __half g_WT [688128];             // weights pre-transposed, half
__device__ int    g_deg[NT];
__device__ int    g_off[NT];
__device__ int    g_cur[NT];
__device__ int    g_srcSorted[2 * EE];

// WT offsets (half elements)
// WT1c: combined [1024 n][128 k]: rows 0-511 = W1_top^T, rows 512-1023 = W1_bot^T
#define WT1_OFF   0
#define WT2_OFF   131072     // mW2^T  [256][512]
#define WTU1_OFF  262144     // uW1^T  [512][512]
#define WTU2_OFF  524288     // uW2^T  [256][512]
#define WTU3_OFF  655360     // uW3^T  [128][256]

__device__ __forceinline__ uint32_t smem_u32(const void* p) {
    return (uint32_t)__cvta_generic_to_shared(p);
}

__device__ __forceinline__ void cp16s(uint32_t dst, const void* src) {
    asm volatile("cp.async.ca.shared.global [%0], [%1], 16;\n" :: "r"(dst), "l"(src));
}

// fp16 MMA m16n8k16, fp32 accumulate
__device__ __forceinline__ void mma16(float* c,
                                      uint32_t a0, uint32_t a1, uint32_t a2, uint32_t a3,
                                      uint32_t b0, uint32_t b1) {
    asm volatile(
        "mma.sync.aligned.m16n8k16.row.col.f32.f16.f16.f32 "
        "{%0,%1,%2,%3}, {%4,%5,%6,%7}, {%8,%9}, {%0,%1,%2,%3};\n"
        : "+f"(c[0]), "+f"(c[1]), "+f"(c[2]), "+f"(c[3])
        : "r"(a0), "r"(a1), "r"(a2), "r"(a3), "r"(b0), "r"(b1));
}

// ---------------- weight transpose: W[K,N] -> WT[N,K], half --------------------
// 6 jobs; job 0/1 build the combined WT1c (top K-half rows 0-511, bottom rows 512+)
__global__ void wtrans_kernel(const float* __restrict__ mW1, const float* __restrict__ mW2,
                              const float* __restrict__ uW1, const float* __restrict__ uW2,
                              const float* __restrict__ uW3) {
    __shared__ float t[32][33];
    int z = blockIdx.z;
    const float* W; __half* D; int K, N, sk = 0;
    switch (z) {
        case 0:  W = mW1; D = g_WT;              K = 128; N = 512; sk = 0;   break;
        case 1:  W = mW1; D = g_WT + 512 * 128;  K = 128; N = 512; sk = 128; break;
        case 2:  W = mW2; D = g_WT + WT2_OFF;    K = 512; N = 256; break;
        case 3:  W = uW1; D = g_WT + WTU1_OFF;   K = 512; N = 512; break;
        case 4:  W = uW2; D = g_WT + WTU2_OFF;   K = 512; N = 256; break;
        default: W = uW3; D = g_WT + WTU3_OFF;   K = 256; N = 128; break;
    }
    int n0 = blockIdx.x * 32, k0 = blockIdx.y * 32;
    if (n0 >= N || k0 >= K) return;
    int tx = threadIdx.x & 31, ty = threadIdx.x >> 5;
#pragma unroll
    for (int i = 0; i < 4; i++)
        t[ty + 8 * i][tx] = W[(size_t)(sk + k0 + ty + 8 * i) * N + n0 + tx];
    __syncthreads();
#pragma unroll
    for (int i = 0; i < 4; i++)
        D[(size_t)(n0 + ty + 8 * i) * K + k0 + tx] = __float2half_rn(t[tx][ty + 8 * i]);
}

// ---------------- small prep kernels -----------------------------------------
__global__ void copy_x_kernel(const float* __restrict__ x1, const float* __restrict__ x2) {
    int idx = blockIdx.x * 256 + threadIdx.x;
    if (idx >= NT * DF) return;
    int n = idx >> 7;
    int d = idx & 127;
    float v = (n < NN) ? x1[idx] : x2[idx - (size_t)NN * DF];
    g_XS[idx] = v;
    __half h = __float2half_rn(v);
    g_XRh[idx] = h;
    g_U[(size_t)n * 512 + 384 + d] = h;
}

__global__ void hist_kernel(const int* __restrict__ ei1, const int* __restrict__ ei2) {
    int e = blockIdx.x * 256 + threadIdx.x;
    if (e < EE)           atomicAdd(&g_deg[ei1[e]], 1);
    else if (e < 2 * EE)  atomicAdd(&g_deg[NN + ei2[e - EE]], 1);
}

__global__ void scan_kernel() {
    __shared__ int wsum[32];
    int t = threadIdx.x;
    int lane = t & 31, wid = t >> 5;
    int base = t * 16;
    int loc[16];
    int s = 0;
#pragma unroll
    for (int i = 0; i < 16; i++) { loc[i] = g_deg[base + i]; s += loc[i]; }
    int inc = s;
#pragma unroll
    for (int d = 1; d < 32; d <<= 1) {
        int v = __shfl_up_sync(0xFFFFFFFFu, inc, d);
        if (lane >= d) inc += v;
    }
    if (lane == 31) wsum[wid] = inc;
    __syncthreads();
    if (wid == 0) {
        int v = wsum[lane];
#pragma unroll
        for (int d = 1; d < 32; d <<= 1) {
            int u = __shfl_up_sync(0xFFFFFFFFu, v, d);
            if (lane >= d) v += u;
        }
        wsum[lane] = v;
    }
    __syncthreads();
    int ex = inc - s + (wid > 0 ? wsum[wid - 1] : 0);
#pragma unroll
    for (int i = 0; i < 16; i++) {
        g_off[base + i] = ex;
        g_cur[base + i] = ex;
        ex += loc[i];
    }
}

__global__ void scatter_kernel(const int* __restrict__ ei1, const int* __restrict__ ei2) {
    int e = blockIdx.x * 256 + threadIdx.x;
    if (e < EE) {
        int tgt = ei1[e];
        int src = ei1[EE + e];
        int p = atomicAdd(&g_cur[tgt], 1);
        g_srcSorted[p] = src;
    } else if (e < 2 * EE) {
        int e2 = e - EE;
        int tgt = ei2[e2];
        int src = ei2[EE + e2];
        int p = atomicAdd(&g_cur[NN + tgt], 1);
        g_srcSorted[p] = NN + src;
    }
}

// One block (64 threads) per target node: H[t] = sum_e relu(A[src] + C[t]).
// A = g_AC[.][0:512], C = g_AC[.][512:1024]; half in, fp32 acc, half out.
__global__ void edge_acc_kernel() {
    int t = blockIdx.x;
    int tid = threadIdx.x;    // 0..63, 8 half columns each (16B)
    const uint4 cu = *(const uint4*)(g_AC + (size_t)t * 1024 + 512 + tid * 8);
    const __half2* ch = (const __half2*)&cu;
    float2 c0 = __half22float2(ch[0]), c1 = __half22float2(ch[1]);
    float2 c2 = __half22float2(ch[2]), c3 = __half22float2(ch[3]);
    float s0 = 0.f, s1 = 0.f, s2 = 0.f, s3 = 0.f;
    float s4 = 0.f, s5 = 0.f, s6 = 0.f, s7 = 0.f;
    int beg = g_off[t];
    int dg  = g_deg[t];
    for (int e = beg; e < beg + dg; e++) {
        int s = g_srcSorted[e];
        const uint4 au = *(const uint4*)(g_AC + (size_t)s * 1024 + tid * 8);
        const __half2* ah = (const __half2*)&au;
        float2 f0 = __half22float2(ah[0]), f1 = __half22float2(ah[1]);
        float2 f2 = __half22float2(ah[2]), f3 = __half22float2(ah[3]);
        s0 += fmaxf(f0.x + c0.x, 0.f); s1 += fmaxf(f0.y + c0.y, 0.f);
        s2 += fmaxf(f1.x + c1.x, 0.f); s3 += fmaxf(f1.y + c1.y, 0.f);
        s4 += fmaxf(f2.x + c2.x, 0.f); s5 += fmaxf(f2.y + c2.y, 0.f);
        s6 += fmaxf(f3.x + c3.x, 0.f); s7 += fmaxf(f3.y + c3.y, 0.f);
    }
    uint4 o;
    __half2* oh = (__half2*)&o;
    oh[0] = __floats2half2_rn(s0, s1);
    oh[1] = __floats2half2_rn(s2, s3);
    oh[2] = __floats2half2_rn(s4, s5);
    oh[3] = __floats2half2_rn(s6, s7);
    *(uint4*)(g_H + (size_t)t * 512 + tid * 8) = o;
}

// ---------------- attention: scores + softmax stats -> P1, P2T ---------------
__global__ void att_scores(const float* __restrict__ x1, const float* __restrict__ x2,
                           float* __restrict__ P1, float* __restrict__ P2T) {
    extern __shared__ float sm[];
    float* X1T = sm;
    float* X2T = sm + 128 * PAD;
    float* S   = sm + 2 * 128 * PAD;
    __shared__ float rmax[128], rsum[128], er[128], ecinv[128], w2[128];

    int g = blockIdx.x;
    int tid = threadIdx.x;
    const float* x1g = x1 + (size_t)g * GNODES * DF;
    const float* x2g = x2 + (size_t)g * GNODES * DF;

    for (int idx = tid; idx < GNODES * DF; idx += 256) {
        int i = idx >> 7, d = idx & 127;
        X1T[d * PAD + i] = x1g[idx];
        X2T[d * PAD + i] = x2g[idx];
    }
    __syncthreads();

    int tx = tid & 15, ty = tid >> 4;
    float acc[8][8];
#pragma unroll
    for (int i = 0; i < 8; i++)
#pragma unroll
        for (int j = 0; j < 8; j++) acc[i][j] = 0.f;

    for (int d = 0; d < 128; d++) {
        float ra[8], rb[8];
        *(float4*)&ra[0] = *(const float4*)&X1T[d * PAD + ty * 8];
        *(float4*)&ra[4] = *(const float4*)&X1T[d * PAD + ty * 8 + 4];
        *(float4*)&rb[0] = *(const float4*)&X2T[d * PAD + tx * 8];
        *(float4*)&rb[4] = *(const float4*)&X2T[d * PAD + tx * 8 + 4];
#pragma unroll
        for (int i = 0; i < 8; i++)
#pragma unroll
            for (int j = 0; j < 8; j++) acc[i][j] += ra[i] * rb[j];
    }
#pragma unroll
    for (int i = 0; i < 8; i++) {
        *(float4*)&S[(ty * 8 + i) * PAD + tx * 8]     = *(float4*)&acc[i][0];
        *(float4*)&S[(ty * 8 + i) * PAD + tx * 8 + 4] = *(float4*)&acc[i][4];
    }
    __syncthreads();

    if (tid < 128) {
        int i = tid;
        float m = -1e30f;
        for (int j = 0; j < 128; j++) m = fmaxf(m, S[i * PAD + j]);
        rmax[i] = m;
        er[i] = expf(m);
    } else {
        int j = tid - 128;
        float m = -1e30f;
        for (int i = 0; i < 128; i++) m = fmaxf(m, S[i * PAD + j]);
        ecinv[j] = expf(-m);
    }
    __syncthreads();

    if (tid < 128) {
        int i = tid;
        float m = rmax[i];
        float s = 0.f;
        for (int j = 0; j < 128; j++) {
            float v = expf(S[i * PAD + j] - m);
            S[i * PAD + j] = v;
            s += v;
        }
        rsum[i] = s;
    }
    __syncthreads();

    if (tid >= 128) {
        int j = tid - 128;
        float s = 0.f;
        for (int i = 0; i < 128; i++) s += S[i * PAD + j] * er[i];
        float cs = s * ecinv[j];
        w2[j] = ecinv[j] / cs;
    }
    __syncthreads();

    float* P1g = P1  + (size_t)g * GNODES * GNODES;
    float* P2g = P2T + (size_t)g * GNODES * GNODES;
    for (int idx = tid; idx < GNODES * GNODES; idx += 256) {
        int i = idx >> 7, j = idx & 127;
        P1g[idx] = S[i * PAD + j] / rsum[i];
    }
    for (int idx = tid; idx < GNODES * GNODES; idx += 256) {
        int j = idx >> 7, i = idx & 127;
        P2g[idx] = S[i * PAD + j] * er[i] * w2[j];
    }
}

// grid=(64,2): z=0 -> att1 = x1 - P1 @ x2 ; z=1 -> att2 = x2 - P2^T @ x1
__global__ void att_apply(const float* __restrict__ x1, const float* __restrict__ x2,
                          const float* __restrict__ P1, const float* __restrict__ P2T) {
    extern __shared__ float sm[];
    float* As = sm;
    float* Bs = sm + 128 * PAD;
    int g = blockIdx.x, z = blockIdx.y;
    const float* Ag; const float* Bg; const float* baseg; int rowBase;
    if (z == 0) {
        Ag = P1  + (size_t)g * GNODES * GNODES;
        Bg = x2  + (size_t)g * GNODES * DF;
        baseg = x1 + (size_t)g * GNODES * DF;
        rowBase = g * GNODES;
    } else {
        Ag = P2T + (size_t)g * GNODES * GNODES;
        Bg = x1  + (size_t)g * GNODES * DF;
        baseg = x2 + (size_t)g * GNODES * DF;
        rowBase = NN + g * GNODES;
    }
    int tid = threadIdx.x;
    for (int idx = tid; idx < GNODES * GNODES; idx += 256) {
        int m = idx >> 7, k = idx & 127;
        As[k * PAD + m] = Ag[idx];
        Bs[m * PAD + k] = Bg[idx];
    }
    __syncthreads();

    int tx = tid & 15, ty = tid >> 4;
    float acc[8][8];
#pragma unroll
    for (int i = 0; i < 8; i++)
#pragma unroll
        for (int j = 0; j < 8; j++) acc[i][j] = 0.f;

    for (int k = 0; k < 128; k++) {
        float ra[8], rb[8];
        *(float4*)&ra[0] = *(const float4*)&As[k * PAD + ty * 8];
        *(float4*)&ra[4] = *(const float4*)&As[k * PAD + ty * 8 + 4];
        *(float4*)&rb[0] = *(const float4*)&Bs[k * PAD + tx * 8];
        *(float4*)&rb[4] = *(const float4*)&Bs[k * PAD + tx * 8 + 4];
#pragma unroll
        for (int i = 0; i < 8; i++)
#pragma unroll
            for (int j = 0; j < 8; j++) acc[i][j] += ra[i] * rb[j];
    }

#pragma unroll
    for (int i = 0; i < 8; i++) {
        int m = ty * 8 + i;
#pragma unroll
        for (int j = 0; j < 8; j++) {
            int d = tx * 8 + j;
            float v = baseg[m * DF + d] - acc[i][j];
            g_U[(size_t)(rowBase + m) * 512 + 256 + d] = __float2half_rn(v);
        }
    }
}

// ---------------- fp16 tensor-core GEMM, 4-stage cp.async ---------------------
// C[m][n] = sum_k A[m][k] * WT[n][k]  (+bias from col bOff)(+deg scale)(+resid)(relu)
// BM=BN=128, BK=32, 256 threads (8 warps), warp tile 64x32 via m16n8k16.
// Smem per stage: A [128][64B] 8KB + B 8KB; conflict-free loads and stores.
#define HSTG 16384            // bytes per stage (A 8KB + B 8KB)
#define NSTG 4
#define HG_SMEM (NSTG * HSTG)   // 65536 bytes

__global__ __launch_bounds__(256, 2)
void hgemm(const __half* __restrict__ A, int lda,
           const __half* __restrict__ WT, int ldwt,
           const float* __restrict__ bias, int bOff,
           const int*   __restrict__ degv,
           const float* __restrict__ resid, int ldr,
           void* __restrict__ Cout, int ldc,
           int K, int doRelu, int outHalf) {
    extern __shared__ char dsm[];
    const uint32_t sbase = smem_u32(dsm);
    const int tid  = threadIdx.x;
    const int lane = tid & 31, warp = tid >> 5;
    const int wM = warp & 1, wN = warp >> 1;
    const int gidr = lane >> 2, t4 = lane & 3;
    const int brow = blockIdx.y * 128;
    const int bcol = blockIdx.x * 128;

    const __half* Agp = A  + (size_t)brow * lda;
    const __half* Bgp = WT + (size_t)bcol * ldwt;
    const int niter = K >> 5;

    auto load_stage = [&](int s, int k0) {
        uint32_t aB = sbase + s * HSTG;
        uint32_t bB = aB + 8192;
#pragma unroll
        for (int it = 0; it < 2; it++) {
            int c = it * 256 + tid;          // 0..511
            int row = c >> 2, kc = c & 3;
            cp16s(aB + row * 64 + kc * 16, Agp + (size_t)row * lda  + k0 + kc * 8);
            cp16s(bB + row * 64 + kc * 16, Bgp + (size_t)row * ldwt + k0 + kc * 8);
        }
        asm volatile("cp.async.commit_group;" ::: "memory");
    };

    float acc[4][4][4];
#pragma unroll
    for (int mt = 0; mt < 4; mt++)
#pragma unroll
        for (int nt = 0; nt < 4; nt++)
#pragma unroll
            for (int r = 0; r < 4; r++) acc[mt][nt][r] = 0.f;

    // prologue: 3 stages ahead
#pragma unroll
    for (int p = 0; p < NSTG - 1; p++) {
        if (p < niter) load_stage(p, p * 32);
        else asm volatile("cp.async.commit_group;" ::: "memory");
    }

    for (int i = 0; i < niter; i++) {
        asm volatile("cp.async.wait_group 2;" ::: "memory");
        __syncthreads();
        if (i + 3 < niter) load_stage((i + 3) % NSTG, (i + 3) * 32);
        else asm volatile("cp.async.commit_group;" ::: "memory");

        const char* as = dsm + (i % NSTG) * HSTG;
        const char* bs = as + 8192;

        uint32_t ua[4][2][4];
#pragma unroll
        for (int mt = 0; mt < 4; mt++)
#pragma unroll
            for (int h = 0; h < 2; h++) {
                int row = wM * 64 + mt * 16 + gidr + h * 8;
                uint4 v = *(const uint4*)(as + row * 64 + t4 * 16);
                ua[mt][h][0] = v.x; ua[mt][h][1] = v.y;
                ua[mt][h][2] = v.z; ua[mt][h][3] = v.w;
            }
        uint32_t ub[4][4];
#pragma unroll
        for (int nt = 0; nt < 4; nt++) {
            int row = wN * 32 + nt * 8 + gidr;
            uint4 v = *(const uint4*)(bs + row * 64 + t4 * 16);
            ub[nt][0] = v.x; ub[nt][1] = v.y; ub[nt][2] = v.z; ub[nt][3] = v.w;
        }
#pragma unroll
        for (int mt = 0; mt < 4; mt++)
#pragma unroll
            for (int nt = 0; nt < 4; nt++)
#pragma unroll
                for (int j = 0; j < 2; j++) {
                    mma16(acc[mt][nt],
                          ua[mt][0][2 * j], ua[mt][1][2 * j],
                          ua[mt][0][2 * j + 1], ua[mt][1][2 * j + 1],
                          ub[nt][2 * j], ub[nt][2 * j + 1]);
                }
    }

#pragma unroll
    for (int mt = 0; mt < 4; mt++) {
#pragma unroll
        for (int half = 0; half < 2; half++) {
            int row = brow + wM * 64 + mt * 16 + gidr + half * 8;
            float rs = degv ? (float)degv[row] : 1.0f;
#pragma unroll
            for (int nt = 0; nt < 4; nt++) {
                int col = bcol + wN * 32 + nt * 8 + t4 * 2;
                float v0 = acc[mt][nt][half * 2 + 0];
                float v1 = acc[mt][nt][half * 2 + 1];
                if (bias && col >= bOff) {
                    v0 += bias[col - bOff] * rs;
                    v1 += bias[col + 1 - bOff] * rs;
                }
                if (resid) { v0 += resid[(size_t)row * ldr + col];
                             v1 += resid[(size_t)row * ldr + col + 1]; }
                if (doRelu) { v0 = fmaxf(v0, 0.f); v1 = fmaxf(v1, 0.f); }
                if (outHalf) {
                    *(__half2*)((__half*)Cout + (size_t)row * ldc + col) =
                        __floats2half2_rn(v0, v1);
                } else {
                    *(float2*)((float*)Cout + (size_t)row * ldc + col) =
                        make_float2(v0, v1);
                }
            }
        }
    }
}

// ---------------- host ---------------------------------------------------------
extern "C" void kernel_launch(void* const* d_in, const int* in_sizes, int n_in,
                              void* d_out, int out_size) {
    const float* x1  = (const float*)d_in[0];
    const int*   ei1 = (const int*)  d_in[1];
    const float* x2  = (const float*)d_in[3];
    const int*   ei2 = (const int*)  d_in[4];
    const float* mW1 = (const float*)d_in[6];
    const float* mb1 = (const float*)d_in[7];
    const float* mW2 = (const float*)d_in[8];
    const float* mb2 = (const float*)d_in[9];
    const float* uW1 = (const float*)d_in[10];
    const float* ub1 = (const float*)d_in[11];
    const float* uW2 = (const float*)d_in[12];
    const float* ub2 = (const float*)d_in[13];
    const float* uW3 = (const float*)d_in[14];
    const float* ub3 = (const float*)d_in[15];
    float* out = (float*)d_out;

    __half *pAC, *pH, *pU, *pH1, *pH2, *pXR, *pWT;
    float *pXS, *pP1, *pP2;
    int *pdeg;
    cudaGetSymbolAddress((void**)&pAC, g_AC);
    cudaGetSymbolAddress((void**)&pH,  g_H);
    cudaGetSymbolAddress((void**)&pU,  g_U);
    cudaGetSymbolAddress((void**)&pH1, g_H1);
    cudaGetSymbolAddress((void**)&pH2, g_H2);
    cudaGetSymbolAddress((void**)&pXS, g_XS);
    cudaGetSymbolAddress((void**)&pXR, g_XRh);
    cudaGetSymbolAddress((void**)&pP1, g_P1);
    cudaGetSymbolAddress((void**)&pP2, g_P2);
    cudaGetSymbolAddress((void**)&pWT, g_WT);
    cudaGetSymbolAddress((void**)&pdeg, g_deg);

    cudaFuncSetAttribute(hgemm, cudaFuncAttributeMaxDynamicSharedMemorySize,
                         (int)HG_SMEM);
    size_t smA = (size_t)3 * 128 * PAD * sizeof(float);
    cudaFuncSetAttribute(att_scores, cudaFuncAttributeMaxDynamicSharedMemorySize, (int)smA);
    size_t smB = (size_t)2 * 128 * PAD * sizeof(float);
    cudaFuncSetAttribute(att_apply, cudaFuncAttributeMaxDynamicSharedMemorySize, (int)smB);

    // Fork attention onto a side stream (depends only on inputs; joins before G4a).
    cudaStream_t sAtt;
    cudaEvent_t evRoot, evAtt;
    cudaStreamCreateWithFlags(&sAtt, cudaStreamNonBlocking);
    cudaEventCreateWithFlags(&evRoot, cudaEventDisableTiming);
    cudaEventCreateWithFlags(&evAtt, cudaEventDisableTiming);

    cudaEventRecord(evRoot, 0);
    cudaStreamWaitEvent(sAtt, evRoot, 0);
    att_scores<<<GB, 256, smA, sAtt>>>(x1, x2, pP1, pP2);
    att_apply<<<dim3(GB, 2), 256, smB, sAtt>>>(x1, x2, pP1, pP2);
    cudaEventRecord(evAtt, sAtt);

    // Main chain
    cudaMemsetAsync(pdeg, 0, NT * sizeof(int));
    copy_x_kernel<<<(NT * DF) / 256, 256>>>(x1, x2);
    wtrans_kernel<<<dim3(16, 16, 6), 256>>>(mW1, mW2, uW1, uW2, uW3);
    hist_kernel<<<2 * EE / 256, 256>>>(ei1, ei2);

    // G1 merged: AC = XR @ [W1_top | W1_bot]^T (+mb1 on cols 512+)
    hgemm<<<dim3(8, NT / 128), 256, HG_SMEM>>>(
        pXR, 128, pWT + WT1_OFF, 128,
        mb1, 512, nullptr, nullptr, 0, pAC, 1024, 128, 0, 1);

    scan_kernel<<<1, 1024>>>();
    scatter_kernel<<<2 * EE / 256, 256>>>(ei1, ei2);
    edge_acc_kernel<<<NT, 64>>>();

    // G2: U[:,0:256] = H @ mW2 + deg * mb2
    hgemm<<<dim3(2, NT / 128), 256, HG_SMEM>>>(
        pH, 512, pWT + WT2_OFF, 512,
        mb2, 0, pdeg, nullptr, 0, pU, 512, 512, 0, 1);

    // join attention before the update MLP
    cudaStreamWaitEvent(0, evAtt, 0);

    hgemm<<<dim3(4, NT / 128), 256, HG_SMEM>>>(
        pU, 512, pWT + WTU1_OFF, 512,
        ub1, 0, nullptr, nullptr, 0, pH1, 512, 512, 1, 1);
    hgemm<<<dim3(2, NT / 128), 256, HG_SMEM>>>(
        pH1, 512, pWT + WTU2_OFF, 512,
        ub2, 0, nullptr, nullptr, 0, pH2, 256, 512, 1, 1);
    // G5: out = XS + H2 @ uW3 + ub3  (fp32 out, fp32 residual)
    hgemm<<<dim3(1, NT / 128), 256, HG_SMEM>>>(
        pH2, 256, pWT + WTU3_OFF, 256,
        ub3, 0, nullptr, pXS, 128, out, 128, 256, 0, 0);
}

// round 13
// speedup vs baseline: 1.2858x; 1.2858x over previous
#include <cuda_runtime.h>
#include <cuda_fp16.h>
#include <math.h>
#include <stdint.h>

// Problem constants (fixed by reference setup_inputs)
#define NN      8192          // nodes per graph
#define NT      16384         // stacked nodes (2 graphs)
#define DF      128           // feature dim
#define EE      131072        // edges per graph
#define GB      64            // graphs per batch
#define GNODES  128           // nodes per graph-block (NN/GB)
#define PAD     132           // smem row pad for attention kernels

// ---------------- scratch (static device globals; no allocation) -------------
__device__ __half g_AC [(size_t)NT * 1024];  // [A (512) | Cb (512)] per row, half
__device__ __half g_H  [(size_t)NT * 512];   // sum_e relu(A[src]+C[tgt]) (half)
__device__ __half g_U  [(size_t)NT * 512];   // [messages | att | x] (half)
__device__ __half g_H1 [(size_t)NT * 512];
__device__ __half g_H2 [(size_t)NT * 256];
__device__ float  g_XS [(size_t)NT * DF];    // stacked [x1; x2] FULL precision (residual)
__device__ __half g_XRh[(size_t)NT * DF];    // half copy (GEMM input)
__device__ float  g_P1 [(size_t)GB * GNODES * GNODES];
__device__ float  g_P2 [(size_t)GB * GNODES * GNODES];
__device__ __half g_WT [688128];             // weights pre-transposed, half
__device__ int    g_deg[NT];
__device__ int    g_off[NT];
__device__ int    g_cur[NT];
__device__ int    g_srcSorted[2 * EE];

// WT offsets (half elements)
// WT1c: combined [1024 n][128 k]: rows 0-511 = W1_top^T, rows 512-1023 = W1_bot^T
#define WT1_OFF   0
#define WT2_OFF   131072     // mW2^T  [256][512]
#define WTU1_OFF  262144     // uW1^T  [512][512]
#define WTU2_OFF  524288     // uW2^T  [256][512]
#define WTU3_OFF  655360     // uW3^T  [128][256]

__device__ __forceinline__ uint32_t smem_u32(const void* p) {
    return (uint32_t)__cvta_generic_to_shared(p);
}

__device__ __forceinline__ void cp16s(uint32_t dst, const void* src) {
    asm volatile("cp.async.ca.shared.global [%0], [%1], 16;\n" :: "r"(dst), "l"(src));
}

// fp16 MMA m16n8k16, fp32 accumulate
__device__ __forceinline__ void mma16(float* c,
                                      uint32_t a0, uint32_t a1, uint32_t a2, uint32_t a3,
                                      uint32_t b0, uint32_t b1) {
    asm volatile(
        "mma.sync.aligned.m16n8k16.row.col.f32.f16.f16.f32 "
        "{%0,%1,%2,%3}, {%4,%5,%6,%7}, {%8,%9}, {%0,%1,%2,%3};\n"
        : "+f"(c[0]), "+f"(c[1]), "+f"(c[2]), "+f"(c[3])
        : "r"(a0), "r"(a1), "r"(a2), "r"(a3), "r"(b0), "r"(b1));
}

// ---------------- weight transpose: W[K,N] -> WT[N,K], half --------------------
// 6 jobs; job 0/1 build the combined WT1c (top K-half rows 0-511, bottom rows 512+)
__global__ void wtrans_kernel(const float* __restrict__ mW1, const float* __restrict__ mW2,
                              const float* __restrict__ uW1, const float* __restrict__ uW2,
                              const float* __restrict__ uW3) {
    __shared__ float t[32][33];
    int z = blockIdx.z;
    const float* W; __half* D; int K, N, sk = 0;
    switch (z) {
        case 0:  W = mW1; D = g_WT;              K = 128; N = 512; sk = 0;   break;
        case 1:  W = mW1; D = g_WT + 512 * 128;  K = 128; N = 512; sk = 128; break;
        case 2:  W = mW2; D = g_WT + WT2_OFF;    K = 512; N = 256; break;
        case 3:  W = uW1; D = g_WT + WTU1_OFF;   K = 512; N = 512; break;
        case 4:  W = uW2; D = g_WT + WTU2_OFF;   K = 512; N = 256; break;
        default: W = uW3; D = g_WT + WTU3_OFF;   K = 256; N = 128; break;
    }
    int n0 = blockIdx.x * 32, k0 = blockIdx.y * 32;
    if (n0 >= N || k0 >= K) return;
    int tx = threadIdx.x & 31, ty = threadIdx.x >> 5;
#pragma unroll
    for (int i = 0; i < 4; i++)
        t[ty + 8 * i][tx] = W[(size_t)(sk + k0 + ty + 8 * i) * N + n0 + tx];
    __syncthreads();
#pragma unroll
    for (int i = 0; i < 4; i++)
        D[(size_t)(n0 + ty + 8 * i) * K + k0 + tx] = __float2half_rn(t[tx][ty + 8 * i]);
}

// ---------------- small prep kernels -----------------------------------------
__global__ void copy_x_kernel(const float* __restrict__ x1, const float* __restrict__ x2) {
    int idx = blockIdx.x * 256 + threadIdx.x;
    if (idx >= NT * DF) return;
    int n = idx >> 7;
    int d = idx & 127;
    float v = (n < NN) ? x1[idx] : x2[idx - (size_t)NN * DF];
    g_XS[idx] = v;
    __half h = __float2half_rn(v);
    g_XRh[idx] = h;
    g_U[(size_t)n * 512 + 384 + d] = h;
}

__global__ void hist_kernel(const int* __restrict__ ei1, const int* __restrict__ ei2) {
    int e = blockIdx.x * 256 + threadIdx.x;
    if (e < EE)           atomicAdd(&g_deg[ei1[e]], 1);
    else if (e < 2 * EE)  atomicAdd(&g_deg[NN + ei2[e - EE]], 1);
}

__global__ void scan_kernel() {
    __shared__ int wsum[32];
    int t = threadIdx.x;
    int lane = t & 31, wid = t >> 5;
    int base = t * 16;
    int loc[16];
    int s = 0;
#pragma unroll
    for (int i = 0; i < 16; i++) { loc[i] = g_deg[base + i]; s += loc[i]; }
    int inc = s;
#pragma unroll
    for (int d = 1; d < 32; d <<= 1) {
        int v = __shfl_up_sync(0xFFFFFFFFu, inc, d);
        if (lane >= d) inc += v;
    }
    if (lane == 31) wsum[wid] = inc;
    __syncthreads();
    if (wid == 0) {
        int v = wsum[lane];
#pragma unroll
        for (int d = 1; d < 32; d <<= 1) {
            int u = __shfl_up_sync(0xFFFFFFFFu, v, d);
            if (lane >= d) v += u;
        }
        wsum[lane] = v;
    }
    __syncthreads();
    int ex = inc - s + (wid > 0 ? wsum[wid - 1] : 0);
#pragma unroll
    for (int i = 0; i < 16; i++) {
        g_off[base + i] = ex;
        g_cur[base + i] = ex;
        ex += loc[i];
    }
}

__global__ void scatter_kernel(const int* __restrict__ ei1, const int* __restrict__ ei2) {
    int e = blockIdx.x * 256 + threadIdx.x;
    if (e < EE) {
        int tgt = ei1[e];
        int src = ei1[EE + e];
        int p = atomicAdd(&g_cur[tgt], 1);
        g_srcSorted[p] = src;
    } else if (e < 2 * EE) {
        int e2 = e - EE;
        int tgt = ei2[e2];
        int src = ei2[EE + e2];
        int p = atomicAdd(&g_cur[NN + tgt], 1);
        g_srcSorted[p] = NN + src;
    }
}

// One block (64 threads) per target node: H[t] = sum_e relu(A[src] + C[t]).
// A = g_AC[.][0:512], C = g_AC[.][512:1024]; half in, fp32 acc, half out.
__global__ void edge_acc_kernel() {
    int t = blockIdx.x;
    int tid = threadIdx.x;    // 0..63, 8 half columns each (16B)
    const uint4 cu = *(const uint4*)(g_AC + (size_t)t * 1024 + 512 + tid * 8);
    const __half2* ch = (const __half2*)&cu;
    float2 c0 = __half22float2(ch[0]), c1 = __half22float2(ch[1]);
    float2 c2 = __half22float2(ch[2]), c3 = __half22float2(ch[3]);
    float s0 = 0.f, s1 = 0.f, s2 = 0.f, s3 = 0.f;
    float s4 = 0.f, s5 = 0.f, s6 = 0.f, s7 = 0.f;
    int beg = g_off[t];
    int dg  = g_deg[t];
    for (int e = beg; e < beg + dg; e++) {
        int s = g_srcSorted[e];
        const uint4 au = *(const uint4*)(g_AC + (size_t)s * 1024 + tid * 8);
        const __half2* ah = (const __half2*)&au;
        float2 f0 = __half22float2(ah[0]), f1 = __half22float2(ah[1]);
        float2 f2 = __half22float2(ah[2]), f3 = __half22float2(ah[3]);
        s0 += fmaxf(f0.x + c0.x, 0.f); s1 += fmaxf(f0.y + c0.y, 0.f);
        s2 += fmaxf(f1.x + c1.x, 0.f); s3 += fmaxf(f1.y + c1.y, 0.f);
        s4 += fmaxf(f2.x + c2.x, 0.f); s5 += fmaxf(f2.y + c2.y, 0.f);
        s6 += fmaxf(f3.x + c3.x, 0.f); s7 += fmaxf(f3.y + c3.y, 0.f);
    }
    uint4 o;
    __half2* oh = (__half2*)&o;
    oh[0] = __floats2half2_rn(s0, s1);
    oh[1] = __floats2half2_rn(s2, s3);
    oh[2] = __floats2half2_rn(s4, s5);
    oh[3] = __floats2half2_rn(s6, s7);
    *(uint4*)(g_H + (size_t)t * 512 + tid * 8) = o;
}

// ---------------- attention: scores + softmax stats -> P1, P2T ---------------
__global__ void att_scores(const float* __restrict__ x1, const float* __restrict__ x2,
                           float* __restrict__ P1, float* __restrict__ P2T) {
    extern __shared__ float sm[];
    float* X1T = sm;
    float* X2T = sm + 128 * PAD;
    float* S   = sm + 2 * 128 * PAD;
    __shared__ float rmax[128], rsum[128], er[128], ecinv[128], w2[128];

    int g = blockIdx.x;
    int tid = threadIdx.x;
    const float* x1g = x1 + (size_t)g * GNODES * DF;
    const float* x2g = x2 + (size_t)g * GNODES * DF;

    for (int idx = tid; idx < GNODES * DF; idx += 256) {
        int i = idx >> 7, d = idx & 127;
        X1T[d * PAD + i] = x1g[idx];
        X2T[d * PAD + i] = x2g[idx];
    }
    __syncthreads();

    int tx = tid & 15, ty = tid >> 4;
    float acc[8][8];
#pragma unroll
    for (int i = 0; i < 8; i++)
#pragma unroll
        for (int j = 0; j < 8; j++) acc[i][j] = 0.f;

    for (int d = 0; d < 128; d++) {
        float ra[8], rb[8];
        *(float4*)&ra[0] = *(const float4*)&X1T[d * PAD + ty * 8];
        *(float4*)&ra[4] = *(const float4*)&X1T[d * PAD + ty * 8 + 4];
        *(float4*)&rb[0] = *(const float4*)&X2T[d * PAD + tx * 8];
        *(float4*)&rb[4] = *(const float4*)&X2T[d * PAD + tx * 8 + 4];
#pragma unroll
        for (int i = 0; i < 8; i++)
#pragma unroll
            for (int j = 0; j < 8; j++) acc[i][j] += ra[i] * rb[j];
    }
#pragma unroll
    for (int i = 0; i < 8; i++) {
        *(float4*)&S[(ty * 8 + i) * PAD + tx * 8]     = *(float4*)&acc[i][0];
        *(float4*)&S[(ty * 8 + i) * PAD + tx * 8 + 4] = *(float4*)&acc[i][4];
    }
    __syncthreads();

    if (tid < 128) {
        int i = tid;
        float m = -1e30f;
        for (int j = 0; j < 128; j++) m = fmaxf(m, S[i * PAD + j]);
        rmax[i] = m;
        er[i] = expf(m);
    } else {
        int j = tid - 128;
        float m = -1e30f;
        for (int i = 0; i < 128; i++) m = fmaxf(m, S[i * PAD + j]);
        ecinv[j] = expf(-m);
    }
    __syncthreads();

    if (tid < 128) {
        int i = tid;
        float m = rmax[i];
        float s = 0.f;
        for (int j = 0; j < 128; j++) {
            float v = expf(S[i * PAD + j] - m);
            S[i * PAD + j] = v;
            s += v;
        }
        rsum[i] = s;
    }
    __syncthreads();

    if (tid >= 128) {
        int j = tid - 128;
        float s = 0.f;
        for (int i = 0; i < 128; i++) s += S[i * PAD + j] * er[i];
        float cs = s * ecinv[j];
        w2[j] = ecinv[j] / cs;
    }
    __syncthreads();

    float* P1g = P1  + (size_t)g * GNODES * GNODES;
    float* P2g = P2T + (size_t)g * GNODES * GNODES;
    for (int idx = tid; idx < GNODES * GNODES; idx += 256) {
        int i = idx >> 7, j = idx & 127;
        P1g[idx] = S[i * PAD + j] / rsum[i];
    }
    for (int idx = tid; idx < GNODES * GNODES; idx += 256) {
        int j = idx >> 7, i = idx & 127;
        P2g[idx] = S[i * PAD + j] * er[i] * w2[j];
    }
}

// grid=(64,2): z=0 -> att1 = x1 - P1 @ x2 ; z=1 -> att2 = x2 - P2^T @ x1
__global__ void att_apply(const float* __restrict__ x1, const float* __restrict__ x2,
                          const float* __restrict__ P1, const float* __restrict__ P2T) {
    extern __shared__ float sm[];
    float* As = sm;
    float* Bs = sm + 128 * PAD;
    int g = blockIdx.x, z = blockIdx.y;
    const float* Ag; const float* Bg; const float* baseg; int rowBase;
    if (z == 0) {
        Ag = P1  + (size_t)g * GNODES * GNODES;
        Bg = x2  + (size_t)g * GNODES * DF;
        baseg = x1 + (size_t)g * GNODES * DF;
        rowBase = g * GNODES;
    } else {
        Ag = P2T + (size_t)g * GNODES * GNODES;
        Bg = x1  + (size_t)g * GNODES * DF;
        baseg = x2 + (size_t)g * GNODES * DF;
        rowBase = NN + g * GNODES;
    }
    int tid = threadIdx.x;
    for (int idx = tid; idx < GNODES * GNODES; idx += 256) {
        int m = idx >> 7, k = idx & 127;
        As[k * PAD + m] = Ag[idx];
        Bs[m * PAD + k] = Bg[idx];
    }
    __syncthreads();

    int tx = tid & 15, ty = tid >> 4;
    float acc[8][8];
#pragma unroll
    for (int i = 0; i < 8; i++)
#pragma unroll
        for (int j = 0; j < 8; j++) acc[i][j] = 0.f;

    for (int k = 0; k < 128; k++) {
        float ra[8], rb[8];
        *(float4*)&ra[0] = *(const float4*)&As[k * PAD + ty * 8];
        *(float4*)&ra[4] = *(const float4*)&As[k * PAD + ty * 8 + 4];
        *(float4*)&rb[0] = *(const float4*)&Bs[k * PAD + tx * 8];
        *(float4*)&rb[4] = *(const float4*)&Bs[k * PAD + tx * 8 + 4];
#pragma unroll
        for (int i = 0; i < 8; i++)
#pragma unroll
            for (int j = 0; j < 8; j++) acc[i][j] += ra[i] * rb[j];
    }

#pragma unroll
    for (int i = 0; i < 8; i++) {
        int m = ty * 8 + i;
#pragma unroll
        for (int j = 0; j < 8; j++) {
            int d = tx * 8 + j;
            float v = baseg[m * DF + d] - acc[i][j];
            g_U[(size_t)(rowBase + m) * 512 + 256 + d] = __float2half_rn(v);
        }
    }
}

// ---------------- fp16 tensor-core GEMM, 4-stage cp.async ---------------------
// C[m][n] = sum_k A[m][k] * WT[n][k]  (+bias from col bOff)(+deg scale)(+resid)(relu)
// BM=BN=128, BK=32, 256 threads (8 warps), warp tile 64x32 via m16n8k16.
#define HSTG 16384            // bytes per stage (A 8KB + B 8KB)
#define NSTG 4
#define HG_SMEM (NSTG * HSTG)   // 65536 bytes

__global__ __launch_bounds__(256, 2)
void hgemm(const __half* __restrict__ A, int lda,
           const __half* __restrict__ WT, int ldwt,
           const float* __restrict__ bias, int bOff,
           const int*   __restrict__ degv,
           const float* __restrict__ resid, int ldr,
           void* __restrict__ Cout, int ldc,
           int K, int doRelu, int outHalf) {
    extern __shared__ char dsm[];
    const uint32_t sbase = smem_u32(dsm);
    const int tid  = threadIdx.x;
    const int lane = tid & 31, warp = tid >> 5;
    const int wM = warp & 1, wN = warp >> 1;
    const int gidr = lane >> 2, t4 = lane & 3;
    const int brow = blockIdx.y * 128;
    const int bcol = blockIdx.x * 128;

    const __half* Agp = A  + (size_t)brow * lda;
    const __half* Bgp = WT + (size_t)bcol * ldwt;
    const int niter = K >> 5;

    auto load_stage = [&](int s, int k0) {
        uint32_t aB = sbase + s * HSTG;
        uint32_t bB = aB + 8192;
#pragma unroll
        for (int it = 0; it < 2; it++) {
            int c = it * 256 + tid;          // 0..511
            int row = c >> 2, kc = c & 3;
            cp16s(aB + row * 64 + kc * 16, Agp + (size_t)row * lda  + k0 + kc * 8);
            cp16s(bB + row * 64 + kc * 16, Bgp + (size_t)row * ldwt + k0 + kc * 8);
        }
        asm volatile("cp.async.commit_group;" ::: "memory");
    };

    float acc[4][4][4];
#pragma unroll
    for (int mt = 0; mt < 4; mt++)
#pragma unroll
        for (int nt = 0; nt < 4; nt++)
#pragma unroll
            for (int r = 0; r < 4; r++) acc[mt][nt][r] = 0.f;

    // prologue: 3 stages ahead
#pragma unroll
    for (int p = 0; p < NSTG - 1; p++) {
        if (p < niter) load_stage(p, p * 32);
        else asm volatile("cp.async.commit_group;" ::: "memory");
    }

    for (int i = 0; i < niter; i++) {
        asm volatile("cp.async.wait_group 2;" ::: "memory");
        __syncthreads();
        if (i + 3 < niter) load_stage((i + 3) % NSTG, (i + 3) * 32);
        else asm volatile("cp.async.commit_group;" ::: "memory");

        const char* as = dsm + (i % NSTG) * HSTG;
        const char* bs = as + 8192;

        uint32_t ua[4][2][4];
#pragma unroll
        for (int mt = 0; mt < 4; mt++)
#pragma unroll
            for (int h = 0; h < 2; h++) {
                int row = wM * 64 + mt * 16 + gidr + h * 8;
                uint4 v = *(const uint4*)(as + row * 64 + t4 * 16);
                ua[mt][h][0] = v.x; ua[mt][h][1] = v.y;
                ua[mt][h][2] = v.z; ua[mt][h][3] = v.w;
            }
        uint32_t ub[4][4];
#pragma unroll
        for (int nt = 0; nt < 4; nt++) {
            int row = wN * 32 + nt * 8 + gidr;
            uint4 v = *(const uint4*)(bs + row * 64 + t4 * 16);
            ub[nt][0] = v.x; ub[nt][1] = v.y; ub[nt][2] = v.z; ub[nt][3] = v.w;
        }
#pragma unroll
        for (int mt = 0; mt < 4; mt++)
#pragma unroll
            for (int nt = 0; nt < 4; nt++)
#pragma unroll
                for (int j = 0; j < 2; j++) {
                    mma16(acc[mt][nt],
                          ua[mt][0][2 * j], ua[mt][1][2 * j],
                          ua[mt][0][2 * j + 1], ua[mt][1][2 * j + 1],
                          ub[nt][2 * j], ub[nt][2 * j + 1]);
                }
    }

#pragma unroll
    for (int mt = 0; mt < 4; mt++) {
#pragma unroll
        for (int half = 0; half < 2; half++) {
            int row = brow + wM * 64 + mt * 16 + gidr + half * 8;
            float rs = degv ? (float)degv[row] : 1.0f;
#pragma unroll
            for (int nt = 0; nt < 4; nt++) {
                int col = bcol + wN * 32 + nt * 8 + t4 * 2;
                float v0 = acc[mt][nt][half * 2 + 0];
                float v1 = acc[mt][nt][half * 2 + 1];
                if (bias && col >= bOff) {
                    v0 += bias[col - bOff] * rs;
                    v1 += bias[col + 1 - bOff] * rs;
                }
                if (resid) { v0 += resid[(size_t)row * ldr + col];
                             v1 += resid[(size_t)row * ldr + col + 1]; }
                if (doRelu) { v0 = fmaxf(v0, 0.f); v1 = fmaxf(v1, 0.f); }
                if (outHalf) {
                    *(__half2*)((__half*)Cout + (size_t)row * ldc + col) =
                        __floats2half2_rn(v0, v1);
                } else {
                    *(float2*)((float*)Cout + (size_t)row * ldc + col) =
                        make_float2(v0, v1);
                }
            }
        }
    }
}

// ---------------- host ---------------------------------------------------------
extern "C" void kernel_launch(void* const* d_in, const int* in_sizes, int n_in,
                              void* d_out, int out_size) {
    const float* x1  = (const float*)d_in[0];
    const int*   ei1 = (const int*)  d_in[1];
    const float* x2  = (const float*)d_in[3];
    const int*   ei2 = (const int*)  d_in[4];
    const float* mW1 = (const float*)d_in[6];
    const float* mb1 = (const float*)d_in[7];
    const float* mW2 = (const float*)d_in[8];
    const float* mb2 = (const float*)d_in[9];
    const float* uW1 = (const float*)d_in[10];
    const float* ub1 = (const float*)d_in[11];
    const float* uW2 = (const float*)d_in[12];
    const float* ub2 = (const float*)d_in[13];
    const float* uW3 = (const float*)d_in[14];
    const float* ub3 = (const float*)d_in[15];
    float* out = (float*)d_out;

    __half *pAC, *pH, *pU, *pH1, *pH2, *pXR, *pWT;
    float *pXS, *pP1, *pP2;
    int *pdeg;
    cudaGetSymbolAddress((void**)&pAC, g_AC);
    cudaGetSymbolAddress((void**)&pH,  g_H);
    cudaGetSymbolAddress((void**)&pU,  g_U);
    cudaGetSymbolAddress((void**)&pH1, g_H1);
    cudaGetSymbolAddress((void**)&pH2, g_H2);
    cudaGetSymbolAddress((void**)&pXS, g_XS);
    cudaGetSymbolAddress((void**)&pXR, g_XRh);
    cudaGetSymbolAddress((void**)&pP1, g_P1);
    cudaGetSymbolAddress((void**)&pP2, g_P2);
    cudaGetSymbolAddress((void**)&pWT, g_WT);
    cudaGetSymbolAddress((void**)&pdeg, g_deg);

    cudaFuncSetAttribute(hgemm, cudaFuncAttributeMaxDynamicSharedMemorySize,
                         (int)HG_SMEM);
    size_t smA = (size_t)3 * 128 * PAD * sizeof(float);
    cudaFuncSetAttribute(att_scores, cudaFuncAttributeMaxDynamicSharedMemorySize, (int)smA);
    size_t smB = (size_t)2 * 128 * PAD * sizeof(float);
    cudaFuncSetAttribute(att_apply, cudaFuncAttributeMaxDynamicSharedMemorySize, (int)smB);

    // Single stream, sequential (R11 topology). Slot 5 = merged G1.
    cudaMemsetAsync(pdeg, 0, NT * sizeof(int));
    copy_x_kernel<<<(NT * DF) / 256, 256>>>(x1, x2);
    wtrans_kernel<<<dim3(16, 16, 6), 256>>>(mW1, mW2, uW1, uW2, uW3);
    hist_kernel<<<2 * EE / 256, 256>>>(ei1, ei2);

    // G1 merged: AC = XR @ [W1_top | W1_bot]^T (+mb1 on cols 512+)  <- profiled
    hgemm<<<dim3(8, NT / 128), 256, HG_SMEM>>>(
        pXR, 128, pWT + WT1_OFF, 128,
        mb1, 512, nullptr, nullptr, 0, pAC, 1024, 128, 0, 1);

    scan_kernel<<<1, 1024>>>();
    scatter_kernel<<<2 * EE / 256, 256>>>(ei1, ei2);
    edge_acc_kernel<<<NT, 64>>>();

    // G2: U[:,0:256] = H @ mW2 + deg * mb2
    hgemm<<<dim3(2, NT / 128), 256, HG_SMEM>>>(
        pH, 512, pWT + WT2_OFF, 512,
        mb2, 0, pdeg, nullptr, 0, pU, 512, 512, 0, 1);

    // attention
    att_scores<<<GB, 256, smA>>>(x1, x2, pP1, pP2);
    att_apply<<<dim3(GB, 2), 256, smB>>>(x1, x2, pP1, pP2);

    // update MLP
    hgemm<<<dim3(4, NT / 128), 256, HG_SMEM>>>(
        pU, 512, pWT + WTU1_OFF, 512,
        ub1, 0, nullptr, nullptr, 0, pH1, 512, 512, 1, 1);
    hgemm<<<dim3(2, NT / 128), 256, HG_SMEM>>>(
        pH1, 512, pWT + WTU2_OFF, 512,
        ub2, 0, nullptr, nullptr, 0, pH2, 256, 512, 1, 1);
    // G5: out = XS + H2 @ uW3 + ub3  (fp32 out, fp32 residual)
    hgemm<<<dim3(1, NT / 128), 256, HG_SMEM>>>(
        pH2, 256, pWT + WTU3_OFF, 256,
        ub3, 0, nullptr, pXS, 128, out, 128, 256, 0, 0);
}

// round 14
// speedup vs baseline: 1.3212x; 1.0275x over previous
#include <cuda_runtime.h>
#include <cuda_fp16.h>
#include <math.h>
#include <stdint.h>

// Problem constants (fixed by reference setup_inputs)
#define NN      8192          // nodes per graph
#define NT      16384         // stacked nodes (2 graphs)
#define DF      128           // feature dim
#define EE      131072        // edges per graph
#define GB      64            // graphs per batch
#define GNODES  128           // nodes per graph-block (NN/GB)
#define PAD     132           // smem row pad for attention kernels

// ---------------- scratch (static device globals; no allocation) -------------
__device__ __half g_AC [(size_t)NT * 1024];  // [A (512) | Cb (512)] per row, half
__device__ __half g_H  [(size_t)NT * 512];   // sum_e relu(A[src]+C[tgt]) (half)
__device__ __half g_U  [(size_t)NT * 512];   // [messages | att | x] (half)
__device__ __half g_H1 [(size_t)NT * 512];
__device__ __half g_H2 [(size_t)NT * 256];
__device__ float  g_XS [(size_t)NT * DF];    // stacked [x1; x2] FULL precision (residual)
__device__ __half g_XRh[(size_t)NT * DF];    // half copy (GEMM input)
__device__ float  g_P1 [(size_t)GB * GNODES * GNODES];
__device__ float  g_P2 [(size_t)GB * GNODES * GNODES];
__device__ __half g_WT [688128];             // weights pre-transposed, half
__device__ int    g_deg[NT];
__device__ int    g_off[NT];
__device__ int    g_cur[NT];
__device__ int    g_srcSorted[2 * EE];

// WT offsets (half elements)
// WT1c: combined [1024 n][128 k]: rows 0-511 = W1_top^T, rows 512-1023 = W1_bot^T
#define WT1_OFF   0
#define WT2_OFF   131072     // mW2^T  [256][512]
#define WTU1_OFF  262144     // uW1^T  [512][512]
#define WTU2_OFF  524288     // uW2^T  [256][512]
#define WTU3_OFF  655360     // uW3^T  [128][256]

__device__ __forceinline__ uint32_t smem_u32(const void* p) {
    return (uint32_t)__cvta_generic_to_shared(p);
}

__device__ __forceinline__ void cp16s(uint32_t dst, const void* src) {
    asm volatile("cp.async.ca.shared.global [%0], [%1], 16;\n" :: "r"(dst), "l"(src));
}

// fp16 MMA m16n8k16, fp32 accumulate
__device__ __forceinline__ void mma16(float* c,
                                      uint32_t a0, uint32_t a1, uint32_t a2, uint32_t a3,
                                      uint32_t b0, uint32_t b1) {
    asm volatile(
        "mma.sync.aligned.m16n8k16.row.col.f32.f16.f16.f32 "
        "{%0,%1,%2,%3}, {%4,%5,%6,%7}, {%8,%9}, {%0,%1,%2,%3};\n"
        : "+f"(c[0]), "+f"(c[1]), "+f"(c[2]), "+f"(c[3])
        : "r"(a0), "r"(a1), "r"(a2), "r"(a3), "r"(b0), "r"(b1));
}

// ---------------- weight transpose: W[K,N] -> WT[N,K], half --------------------
// 6 jobs; job 0/1 build the combined WT1c (top K-half rows 0-511, bottom rows 512+)
__global__ void wtrans_kernel(const float* __restrict__ mW1, const float* __restrict__ mW2,
                              const float* __restrict__ uW1, const float* __restrict__ uW2,
                              const float* __restrict__ uW3) {
    __shared__ float t[32][33];
    int z = blockIdx.z;
    const float* W; __half* D; int K, N, sk = 0;
    switch (z) {
        case 0:  W = mW1; D = g_WT;              K = 128; N = 512; sk = 0;   break;
        case 1:  W = mW1; D = g_WT + 512 * 128;  K = 128; N = 512; sk = 128; break;
        case 2:  W = mW2; D = g_WT + WT2_OFF;    K = 512; N = 256; break;
        case 3:  W = uW1; D = g_WT + WTU1_OFF;   K = 512; N = 512; break;
        case 4:  W = uW2; D = g_WT + WTU2_OFF;   K = 512; N = 256; break;
        default: W = uW3; D = g_WT + WTU3_OFF;   K = 256; N = 128; break;
    }
    int n0 = blockIdx.x * 32, k0 = blockIdx.y * 32;
    if (n0 >= N || k0 >= K) return;
    int tx = threadIdx.x & 31, ty = threadIdx.x >> 5;
#pragma unroll
    for (int i = 0; i < 4; i++)
        t[ty + 8 * i][tx] = W[(size_t)(sk + k0 + ty + 8 * i) * N + n0 + tx];
    __syncthreads();
#pragma unroll
    for (int i = 0; i < 4; i++)
        D[(size_t)(n0 + ty + 8 * i) * K + k0 + tx] = __float2half_rn(t[tx][ty + 8 * i]);
}

// ---------------- small prep kernels -----------------------------------------
__global__ void copy_x_kernel(const float* __restrict__ x1, const float* __restrict__ x2) {
    int idx = blockIdx.x * 256 + threadIdx.x;
    if (idx >= NT * DF) return;
    int n = idx >> 7;
    int d = idx & 127;
    float v = (n < NN) ? x1[idx] : x2[idx - (size_t)NN * DF];
    g_XS[idx] = v;
    __half h = __float2half_rn(v);
    g_XRh[idx] = h;
    g_U[(size_t)n * 512 + 384 + d] = h;
}

__global__ void hist_kernel(const int* __restrict__ ei1, const int* __restrict__ ei2) {
    int e = blockIdx.x * 256 + threadIdx.x;
    if (e < EE)           atomicAdd(&g_deg[ei1[e]], 1);
    else if (e < 2 * EE)  atomicAdd(&g_deg[NN + ei2[e - EE]], 1);
}

__global__ void scan_kernel() {
    __shared__ int wsum[32];
    int t = threadIdx.x;
    int lane = t & 31, wid = t >> 5;
    int base = t * 16;
    int loc[16];
    int s = 0;
#pragma unroll
    for (int i = 0; i < 16; i++) { loc[i] = g_deg[base + i]; s += loc[i]; }
    int inc = s;
#pragma unroll
    for (int d = 1; d < 32; d <<= 1) {
        int v = __shfl_up_sync(0xFFFFFFFFu, inc, d);
        if (lane >= d) inc += v;
    }
    if (lane == 31) wsum[wid] = inc;
    __syncthreads();
    if (wid == 0) {
        int v = wsum[lane];
#pragma unroll
        for (int d = 1; d < 32; d <<= 1) {
            int u = __shfl_up_sync(0xFFFFFFFFu, v, d);
            if (lane >= d) v += u;
        }
        wsum[lane] = v;
    }
    __syncthreads();
    int ex = inc - s + (wid > 0 ? wsum[wid - 1] : 0);
#pragma unroll
    for (int i = 0; i < 16; i++) {
        g_off[base + i] = ex;
        g_cur[base + i] = ex;
        ex += loc[i];
    }
}

__global__ void scatter_kernel(const int* __restrict__ ei1, const int* __restrict__ ei2) {
    int e = blockIdx.x * 256 + threadIdx.x;
    if (e < EE) {
        int tgt = ei1[e];
        int src = ei1[EE + e];
        int p = atomicAdd(&g_cur[tgt], 1);
        g_srcSorted[p] = src;
    } else if (e < 2 * EE) {
        int e2 = e - EE;
        int tgt = ei2[e2];
        int src = ei2[EE + e2];
        int p = atomicAdd(&g_cur[NN + tgt], 1);
        g_srcSorted[p] = NN + src;
    }
}

// One block (64 threads) per target node: H[t] = sum_e relu(A[src] + C[t]).
// A = g_AC[.][0:512], C = g_AC[.][512:1024]; half in, fp32 acc, half out.
__global__ void edge_acc_kernel() {
    int t = blockIdx.x;
    int tid = threadIdx.x;    // 0..63, 8 half columns each (16B)
    const uint4 cu = *(const uint4*)(g_AC + (size_t)t * 1024 + 512 + tid * 8);
    const __half2* ch = (const __half2*)&cu;
    float2 c0 = __half22float2(ch[0]), c1 = __half22float2(ch[1]);
    float2 c2 = __half22float2(ch[2]), c3 = __half22float2(ch[3]);
    float s0 = 0.f, s1 = 0.f, s2 = 0.f, s3 = 0.f;
    float s4 = 0.f, s5 = 0.f, s6 = 0.f, s7 = 0.f;
    int beg = g_off[t];
    int dg  = g_deg[t];
    for (int e = beg; e < beg + dg; e++) {
        int s = g_srcSorted[e];
        const uint4 au = *(const uint4*)(g_AC + (size_t)s * 1024 + tid * 8);
        const __half2* ah = (const __half2*)&au;
        float2 f0 = __half22float2(ah[0]), f1 = __half22float2(ah[1]);
        float2 f2 = __half22float2(ah[2]), f3 = __half22float2(ah[3]);
        s0 += fmaxf(f0.x + c0.x, 0.f); s1 += fmaxf(f0.y + c0.y, 0.f);
        s2 += fmaxf(f1.x + c1.x, 0.f); s3 += fmaxf(f1.y + c1.y, 0.f);
        s4 += fmaxf(f2.x + c2.x, 0.f); s5 += fmaxf(f2.y + c2.y, 0.f);
        s6 += fmaxf(f3.x + c3.x, 0.f); s7 += fmaxf(f3.y + c3.y, 0.f);
    }
    uint4 o;
    __half2* oh = (__half2*)&o;
    oh[0] = __floats2half2_rn(s0, s1);
    oh[1] = __floats2half2_rn(s2, s3);
    oh[2] = __floats2half2_rn(s4, s5);
    oh[3] = __floats2half2_rn(s6, s7);
    *(uint4*)(g_H + (size_t)t * 512 + tid * 8) = o;
}

// ---------------- attention: scores + softmax stats -> P1, P2T ---------------
__global__ void att_scores(const float* __restrict__ x1, const float* __restrict__ x2,
                           float* __restrict__ P1, float* __restrict__ P2T) {
    extern __shared__ float sm[];
    float* X1T = sm;
    float* X2T = sm + 128 * PAD;
    float* S   = sm + 2 * 128 * PAD;
    __shared__ float rmax[128], rsum[128], er[128], ecinv[128], w2[128];

    int g = blockIdx.x;
    int tid = threadIdx.x;
    const float* x1g = x1 + (size_t)g * GNODES * DF;
    const float* x2g = x2 + (size_t)g * GNODES * DF;

    for (int idx = tid; idx < GNODES * DF; idx += 256) {
        int i = idx >> 7, d = idx & 127;
        X1T[d * PAD + i] = x1g[idx];
        X2T[d * PAD + i] = x2g[idx];
    }
    __syncthreads();

    int tx = tid & 15, ty = tid >> 4;
    float acc[8][8];
#pragma unroll
    for (int i = 0; i < 8; i++)
#pragma unroll
        for (int j = 0; j < 8; j++) acc[i][j] = 0.f;

    for (int d = 0; d < 128; d++) {
        float ra[8], rb[8];
        *(float4*)&ra[0] = *(const float4*)&X1T[d * PAD + ty * 8];
        *(float4*)&ra[4] = *(const float4*)&X1T[d * PAD + ty * 8 + 4];
        *(float4*)&rb[0] = *(const float4*)&X2T[d * PAD + tx * 8];
        *(float4*)&rb[4] = *(const float4*)&X2T[d * PAD + tx * 8 + 4];
#pragma unroll
        for (int i = 0; i < 8; i++)
#pragma unroll
            for (int j = 0; j < 8; j++) acc[i][j] += ra[i] * rb[j];
    }
#pragma unroll
    for (int i = 0; i < 8; i++) {
        *(float4*)&S[(ty * 8 + i) * PAD + tx * 8]     = *(float4*)&acc[i][0];
        *(float4*)&S[(ty * 8 + i) * PAD + tx * 8 + 4] = *(float4*)&acc[i][4];
    }
    __syncthreads();

    if (tid < 128) {
        int i = tid;
        float m = -1e30f;
        for (int j = 0; j < 128; j++) m = fmaxf(m, S[i * PAD + j]);
        rmax[i] = m;
        er[i] = expf(m);
    } else {
        int j = tid - 128;
        float m = -1e30f;
        for (int i = 0; i < 128; i++) m = fmaxf(m, S[i * PAD + j]);
        ecinv[j] = expf(-m);
    }
    __syncthreads();

    if (tid < 128) {
        int i = tid;
        float m = rmax[i];
        float s = 0.f;
        for (int j = 0; j < 128; j++) {
            float v = expf(S[i * PAD + j] - m);
            S[i * PAD + j] = v;
            s += v;
        }
        rsum[i] = s;
    }
    __syncthreads();

    if (tid >= 128) {
        int j = tid - 128;
        float s = 0.f;
        for (int i = 0; i < 128; i++) s += S[i * PAD + j] * er[i];
        float cs = s * ecinv[j];
        w2[j] = ecinv[j] / cs;
    }
    __syncthreads();

    float* P1g = P1  + (size_t)g * GNODES * GNODES;
    float* P2g = P2T + (size_t)g * GNODES * GNODES;
    for (int idx = tid; idx < GNODES * GNODES; idx += 256) {
        int i = idx >> 7, j = idx & 127;
        P1g[idx] = S[i * PAD + j] / rsum[i];
    }
    for (int idx = tid; idx < GNODES * GNODES; idx += 256) {
        int j = idx >> 7, i = idx & 127;
        P2g[idx] = S[i * PAD + j] * er[i] * w2[j];
    }
}

// grid=(64,2): z=0 -> att1 = x1 - P1 @ x2 ; z=1 -> att2 = x2 - P2^T @ x1
__global__ void att_apply(const float* __restrict__ x1, const float* __restrict__ x2,
                          const float* __restrict__ P1, const float* __restrict__ P2T) {
    extern __shared__ float sm[];
    float* As = sm;
    float* Bs = sm + 128 * PAD;
    int g = blockIdx.x, z = blockIdx.y;
    const float* Ag; const float* Bg; const float* baseg; int rowBase;
    if (z == 0) {
        Ag = P1  + (size_t)g * GNODES * GNODES;
        Bg = x2  + (size_t)g * GNODES * DF;
        baseg = x1 + (size_t)g * GNODES * DF;
        rowBase = g * GNODES;
    } else {
        Ag = P2T + (size_t)g * GNODES * GNODES;
        Bg = x1  + (size_t)g * GNODES * DF;
        baseg = x2 + (size_t)g * GNODES * DF;
        rowBase = NN + g * GNODES;
    }
    int tid = threadIdx.x;
    for (int idx = tid; idx < GNODES * GNODES; idx += 256) {
        int m = idx >> 7, k = idx & 127;
        As[k * PAD + m] = Ag[idx];
        Bs[m * PAD + k] = Bg[idx];
    }
    __syncthreads();

    int tx = tid & 15, ty = tid >> 4;
    float acc[8][8];
#pragma unroll
    for (int i = 0; i < 8; i++)
#pragma unroll
        for (int j = 0; j < 8; j++) acc[i][j] = 0.f;

    for (int k = 0; k < 128; k++) {
        float ra[8], rb[8];
        *(float4*)&ra[0] = *(const float4*)&As[k * PAD + ty * 8];
        *(float4*)&ra[4] = *(const float4*)&As[k * PAD + ty * 8 + 4];
        *(float4*)&rb[0] = *(const float4*)&Bs[k * PAD + tx * 8];
        *(float4*)&rb[4] = *(const float4*)&Bs[k * PAD + tx * 8 + 4];
#pragma unroll
        for (int i = 0; i < 8; i++)
#pragma unroll
            for (int j = 0; j < 8; j++) acc[i][j] += ra[i] * rb[j];
    }

#pragma unroll
    for (int i = 0; i < 8; i++) {
        int m = ty * 8 + i;
#pragma unroll
        for (int j = 0; j < 8; j++) {
            int d = tx * 8 + j;
            float v = baseg[m * DF + d] - acc[i][j];
            g_U[(size_t)(rowBase + m) * 512 + 256 + d] = __float2half_rn(v);
        }
    }
}

// ---------------- fp16 tensor-core GEMM, 3-stage cp.async ---------------------
// C[m][n] = sum_k A[m][k] * WT[n][k]  (+bias from col bOff)(+deg scale)(+resid)(relu)
// BM=BN=128, BK=32, 256 threads (8 warps), warp tile 64x32 via m16n8k16.
// Bias block-hoisted: bOff is a multiple of 128, so bias applies per-CTA.
#define HSTG 16384            // bytes per stage (A 8KB + B 8KB)
#define NSTG 3
#define HG_SMEM (NSTG * HSTG)   // 49152 bytes

__global__ __launch_bounds__(256, 2)
void hgemm(const __half* __restrict__ A, int lda,
           const __half* __restrict__ WT, int ldwt,
           const float* __restrict__ bias, int bOff,
           const int*   __restrict__ degv,
           const float* __restrict__ resid, int ldr,
           void* __restrict__ Cout, int ldc,
           int K, int doRelu, int outHalf) {
    extern __shared__ char dsm[];
    const uint32_t sbase = smem_u32(dsm);
    const int tid  = threadIdx.x;
    const int lane = tid & 31, warp = tid >> 5;
    const int wM = warp & 1, wN = warp >> 1;
    const int gidr = lane >> 2, t4 = lane & 3;
    const int brow = blockIdx.y * 128;
    const int bcol = blockIdx.x * 128;

    // per-CTA bias hoist (bOff is block-aligned)
    const float* biasBlk = (bias && bcol >= bOff) ? (bias + (bcol - bOff)) : nullptr;

    const __half* Agp = A  + (size_t)brow * lda;
    const __half* Bgp = WT + (size_t)bcol * ldwt;
    const int niter = K >> 5;

    auto load_stage = [&](int s, int k0) {
        uint32_t aB = sbase + s * HSTG;
        uint32_t bB = aB + 8192;
#pragma unroll
        for (int it = 0; it < 2; it++) {
            int c = it * 256 + tid;          // 0..511
            int row = c >> 2, kc = c & 3;
            cp16s(aB + row * 64 + kc * 16, Agp + (size_t)row * lda  + k0 + kc * 8);
            cp16s(bB + row * 64 + kc * 16, Bgp + (size_t)row * ldwt + k0 + kc * 8);
        }
        asm volatile("cp.async.commit_group;" ::: "memory");
    };

    float acc[4][4][4];
#pragma unroll
    for (int mt = 0; mt < 4; mt++)
#pragma unroll
        for (int nt = 0; nt < 4; nt++)
#pragma unroll
            for (int r = 0; r < 4; r++) acc[mt][nt][r] = 0.f;

    load_stage(0, 0);
    if (niter > 1) load_stage(1, 32);
    else asm volatile("cp.async.commit_group;" ::: "memory");

    for (int i = 0; i < niter; i++) {
        asm volatile("cp.async.wait_group 1;" ::: "memory");
        __syncthreads();
        if (i + 2 < niter) load_stage((i + 2) % NSTG, (i + 2) * 32);
        else asm volatile("cp.async.commit_group;" ::: "memory");

        const char* as = dsm + (i % NSTG) * HSTG;
        const char* bs = as + 8192;

        uint32_t ua[4][2][4];
#pragma unroll
        for (int mt = 0; mt < 4; mt++)
#pragma unroll
            for (int h = 0; h < 2; h++) {
                int row = wM * 64 + mt * 16 + gidr + h * 8;
                uint4 v = *(const uint4*)(as + row * 64 + t4 * 16);
                ua[mt][h][0] = v.x; ua[mt][h][1] = v.y;
                ua[mt][h][2] = v.z; ua[mt][h][3] = v.w;
            }
        uint32_t ub[4][4];
#pragma unroll
        for (int nt = 0; nt < 4; nt++) {
            int row = wN * 32 + nt * 8 + gidr;
            uint4 v = *(const uint4*)(bs + row * 64 + t4 * 16);
            ub[nt][0] = v.x; ub[nt][1] = v.y; ub[nt][2] = v.z; ub[nt][3] = v.w;
        }
#pragma unroll
        for (int mt = 0; mt < 4; mt++)
#pragma unroll
            for (int nt = 0; nt < 4; nt++)
#pragma unroll
                for (int j = 0; j < 2; j++) {
                    mma16(acc[mt][nt],
                          ua[mt][0][2 * j], ua[mt][1][2 * j],
                          ua[mt][0][2 * j + 1], ua[mt][1][2 * j + 1],
                          ub[nt][2 * j], ub[nt][2 * j + 1]);
                }
    }

#pragma unroll
    for (int mt = 0; mt < 4; mt++) {
#pragma unroll
        for (int half = 0; half < 2; half++) {
            int row = brow + wM * 64 + mt * 16 + gidr + half * 8;
            float rs = degv ? (float)degv[row] : 1.0f;
#pragma unroll
            for (int nt = 0; nt < 4; nt++) {
                int colL = wN * 32 + nt * 8 + t4 * 2;      // block-local col
                int col  = bcol + colL;
                float v0 = acc[mt][nt][half * 2 + 0];
                float v1 = acc[mt][nt][half * 2 + 1];
                if (biasBlk) { v0 += biasBlk[colL] * rs;  v1 += biasBlk[colL + 1] * rs; }
                if (resid)   { v0 += resid[(size_t)row * ldr + col];
                               v1 += resid[(size_t)row * ldr + col + 1]; }
                if (doRelu)  { v0 = fmaxf(v0, 0.f); v1 = fmaxf(v1, 0.f); }
                if (outHalf) {
                    *(__half2*)((__half*)Cout + (size_t)row * ldc + col) =
                        __floats2half2_rn(v0, v1);
                } else {
                    *(float2*)((float*)Cout + (size_t)row * ldc + col) =
                        make_float2(v0, v1);
                }
            }
        }
    }
}

// ---------------- host ---------------------------------------------------------
extern "C" void kernel_launch(void* const* d_in, const int* in_sizes, int n_in,
                              void* d_out, int out_size) {
    const float* x1  = (const float*)d_in[0];
    const int*   ei1 = (const int*)  d_in[1];
    const float* x2  = (const float*)d_in[3];
    const int*   ei2 = (const int*)  d_in[4];
    const float* mW1 = (const float*)d_in[6];
    const float* mb1 = (const float*)d_in[7];
    const float* mW2 = (const float*)d_in[8];
    const float* mb2 = (const float*)d_in[9];
    const float* uW1 = (const float*)d_in[10];
    const float* ub1 = (const float*)d_in[11];
    const float* uW2 = (const float*)d_in[12];
    const float* ub2 = (const float*)d_in[13];
    const float* uW3 = (const float*)d_in[14];
    const float* ub3 = (const float*)d_in[15];
    float* out = (float*)d_out;

    __half *pAC, *pH, *pU, *pH1, *pH2, *pXR, *pWT;
    float *pXS, *pP1, *pP2;
    int *pdeg;
    cudaGetSymbolAddress((void**)&pAC, g_AC);
    cudaGetSymbolAddress((void**)&pH,  g_H);
    cudaGetSymbolAddress((void**)&pU,  g_U);
    cudaGetSymbolAddress((void**)&pH1, g_H1);
    cudaGetSymbolAddress((void**)&pH2, g_H2);
    cudaGetSymbolAddress((void**)&pXS, g_XS);
    cudaGetSymbolAddress((void**)&pXR, g_XRh);
    cudaGetSymbolAddress((void**)&pP1, g_P1);
    cudaGetSymbolAddress((void**)&pP2, g_P2);
    cudaGetSymbolAddress((void**)&pWT, g_WT);
    cudaGetSymbolAddress((void**)&pdeg, g_deg);

    cudaFuncSetAttribute(hgemm, cudaFuncAttributeMaxDynamicSharedMemorySize,
                         (int)HG_SMEM);
    size_t smA = (size_t)3 * 128 * PAD * sizeof(float);
    cudaFuncSetAttribute(att_scores, cudaFuncAttributeMaxDynamicSharedMemorySize, (int)smA);
    size_t smB = (size_t)2 * 128 * PAD * sizeof(float);
    cudaFuncSetAttribute(att_apply, cudaFuncAttributeMaxDynamicSharedMemorySize, (int)smB);

    // Single stream, sequential. Slot 5 = merged G1.
    cudaMemsetAsync(pdeg, 0, NT * sizeof(int));
    copy_x_kernel<<<(NT * DF) / 256, 256>>>(x1, x2);
    wtrans_kernel<<<dim3(16, 16, 6), 256>>>(mW1, mW2, uW1, uW2, uW3);
    hist_kernel<<<2 * EE / 256, 256>>>(ei1, ei2);

    // G1 merged: AC = XR @ [W1_top | W1_bot]^T (+mb1 on cols 512+)  <- profiled
    hgemm<<<dim3(8, NT / 128), 256, HG_SMEM>>>(
        pXR, 128, pWT + WT1_OFF, 128,
        mb1, 512, nullptr, nullptr, 0, pAC, 1024, 128, 0, 1);

    scan_kernel<<<1, 1024>>>();
    scatter_kernel<<<2 * EE / 256, 256>>>(ei1, ei2);
    edge_acc_kernel<<<NT, 64>>>();

    // G2: U[:,0:256] = H @ mW2 + deg * mb2
    hgemm<<<dim3(2, NT / 128), 256, HG_SMEM>>>(
        pH, 512, pWT + WT2_OFF, 512,
        mb2, 0, pdeg, nullptr, 0, pU, 512, 512, 0, 1);

    // attention
    att_scores<<<GB, 256, smA>>>(x1, x2, pP1, pP2);
    att_apply<<<dim3(GB, 2), 256, smB>>>(x1, x2, pP1, pP2);

    // update MLP
    hgemm<<<dim3(4, NT / 128), 256, HG_SMEM>>>(
        pU, 512, pWT + WTU1_OFF, 512,
        ub1, 0, nullptr, nullptr, 0, pH1, 512, 512, 1, 1);
    hgemm<<<dim3(2, NT / 128), 256, HG_SMEM>>>(
        pH1, 512, pWT + WTU2_OFF, 512,
        ub2, 0, nullptr, nullptr, 0, pH2, 256, 512, 1, 1);
    // G5: out = XS + H2 @ uW3 + ub3  (fp32 out, fp32 residual)
    hgemm<<<dim3(1, NT / 128), 256, HG_SMEM>>>(
        pH2, 256, pWT + WTU3_OFF, 256,
        ub3, 0, nullptr, pXS, 128, out, 128, 256, 0, 0);
}